// round 13
// baseline (speedup 1.0000x reference)
#include <cuda_runtime.h>

// Problem dims (fixed)
#define Bb   2
#define Ss   2048
#define Dd   1024
#define Hh   16
#define KVh  4
#define QKBd 16
#define VBd  32
#define MROWS (Bb*Ss)          // 4096
#define HVB   (Hh*VBd)         // 512
#define NTILES (Ss/64)         // 32

// ---------------- scratch (static device arrays; no allocation) -------------
__device__ __align__(16) float g_pq[Bb*Hh*Ss*QKBd];    // [(b*H+h)*S+s][16]
__device__ __align__(16) float g_pk[Bb*KVh*Ss*QKBd];   // [(b*KV+kv)*S+t][16]
__device__ __align__(16) float g_sk[Bb*KVh*Ss];        // row sums of pk
__device__ __align__(16) float g_pv[Bb*KVh*Ss*VBd];    // [(b*KV+kv)*S+t][32]
__device__ __align__(16) float g_vh[Bb*Ss*HVB];        // [b*S+s][h*32+j]
__device__ __align__(16) float g_bias[Dd];             // e0 @ Wo

// Pre-split K/V in MMA B-fragment layout (hi/lo tf32), one tile = 64 keys.
// K tile: 8 n8 x 2 k8 x 32 lane x 2 j = 1024 u32.  V tile: 4 n8 x 8 k8 x 64 = 2048 u32.
__device__ __align__(16) unsigned g_kfh[Bb*KVh*NTILES*1024];
__device__ __align__(16) unsigned g_kfl[Bb*KVh*NTILES*1024];
__device__ __align__(16) unsigned g_vfh[Bb*KVh*NTILES*2048];
__device__ __align__(16) unsigned g_vfl[Bb*KVh*NTILES*2048];

__device__ __forceinline__ float sigmoidf_fast(float x) {
    return __fdividef(1.f, 1.f + __expf(-x));
}
__device__ __forceinline__ unsigned f2tf(float x) {
    unsigned u; asm("cvt.rna.tf32.f32 %0, %1;" : "=r"(u) : "f"(x)); return u;
}
__device__ __forceinline__ void mma_tf32(
    float& c0, float& c1, float& c2, float& c3,
    unsigned a0, unsigned a1, unsigned a2, unsigned a3,
    unsigned b0, unsigned b1)
{
    asm("mma.sync.aligned.m16n8k8.row.col.f32.tf32.tf32.f32 "
        "{%0,%1,%2,%3},{%4,%5,%6,%7},{%8,%9},{%0,%1,%2,%3};"
        : "+f"(c0), "+f"(c1), "+f"(c2), "+f"(c3)
        : "r"(a0), "r"(a1), "r"(a2), "r"(a3), "r"(b0), "r"(b1));
}

// Fragment-permuted smem layout (GEMMs):
// A tile: blocks of 128 u32; elem (r16,c8): lane=((r&7)<<2)|(c&3), j=(r>>3)|(((c>>2)&1)<<1)
// B tile: blocks of 64 u32;  elem (kr,nc):  lane=(nc<<2)|(kr&3), j=kr>>2

// ---------------- Kernel 1: fused QKV projection (tf32 3-term emulation) ----
__global__ __launch_bounds__(256) void proj_tf32(
    const float* __restrict__ A,
    const float* __restrict__ Wq, const float* __restrict__ Wk,
    const float* __restrict__ Wv)
{
    __shared__ unsigned AsH[4096];
    __shared__ unsigned AsL[4096];
    __shared__ unsigned BsH[2048];
    __shared__ unsigned BsL[2048];

    const int tid  = threadIdx.x;
    const int lane = tid & 31;
    const int warp = tid >> 5;
    const int warpM = warp & 3;
    const int warpN = warp >> 2;
    const int m0 = blockIdx.x * 128;

    const float* W; int N, n0g, mode;
    const int yb = blockIdx.y;
    if (yb < 4)       { W = Wq; N = 256; n0g = yb * 64;       mode = 0; }
    else if (yb == 4) { W = Wk; N = 64;  n0g = 0;             mode = 1; }
    else              { W = Wv; N = 128; n0g = (yb - 5) * 64; mode = 2; }

    float acc[2][4][4];
#pragma unroll
    for (int mt = 0; mt < 2; ++mt)
#pragma unroll
        for (int nt = 0; nt < 4; ++nt)
#pragma unroll
            for (int j = 0; j < 4; ++j) acc[mt][nt][j] = 0.f;

    const int ar  = tid >> 1;
    const int acb = (tid & 1) * 16;
    const int bkr = tid >> 3;
    const int bnb = (tid & 7) * 8;

    for (int k0 = 0; k0 < Dd; k0 += 32) {
        {
            const float* Ap = &A[(m0 + ar) * Dd + k0 + acb];
            float4 q0 = *(const float4*)(Ap + 0);
            float4 q1 = *(const float4*)(Ap + 4);
            float4 q2 = *(const float4*)(Ap + 8);
            float4 q3 = *(const float4*)(Ap + 12);
            float av[16] = {q0.x,q0.y,q0.z,q0.w, q1.x,q1.y,q1.z,q1.w,
                            q2.x,q2.y,q2.z,q2.w, q3.x,q3.y,q3.z,q3.w};
            const int r16 = ar & 15, mt = ar >> 4;
#pragma unroll
            for (int u = 0; u < 16; ++u) {
                const int c  = acb + u;
                const int k8 = c >> 3, c8 = c & 7;
                const int l2 = ((r16 & 7) << 2) | (c8 & 3);
                const int j  = (r16 >> 3) | (((c8 >> 2) & 1) << 1);
                const int idx = ((mt * 4 + k8) * 32 + l2) * 4 + j;
                const float x = av[u];
                const unsigned hb = f2tf(x);
                AsH[idx] = hb;
                AsL[idx] = f2tf(x - __uint_as_float(hb));
            }
        }
        {
            const float* Wp = &W[(k0 + bkr) * N + n0g + bnb];
            float4 w0 = *(const float4*)(Wp + 0);
            float4 w1 = *(const float4*)(Wp + 4);
            float wv[8] = {w0.x,w0.y,w0.z,w0.w, w1.x,w1.y,w1.z,w1.w};
            const int k8 = bkr >> 3, krr = bkr & 7;
#pragma unroll
            for (int u = 0; u < 8; ++u) {
                const int nc = bnb + u;
                const int n8t = nc >> 3, ncc = nc & 7;
                const int idx = ((n8t * 4 + k8) * 32 + ((ncc << 2) | (krr & 3))) * 2 + (krr >> 2);
                const float x = wv[u];
                const unsigned hb = f2tf(x);
                BsH[idx] = hb;
                BsL[idx] = f2tf(x - __uint_as_float(hb));
            }
        }
        __syncthreads();

#pragma unroll
        for (int k8 = 0; k8 < 4; ++k8) {
            uint2 bh[4], bl[4];
#pragma unroll
            for (int nt = 0; nt < 4; ++nt) {
                const int bi = (((warpN*4 + nt) * 4 + k8) * 32 + lane) * 2;
                bh[nt] = *(const uint2*)&BsH[bi];
                bl[nt] = *(const uint2*)&BsL[bi];
            }
#pragma unroll
            for (int mt = 0; mt < 2; ++mt) {
                const int base = (((warpM*2 + mt) * 4 + k8) * 32 + lane) * 4;
                uint4 ah = *(const uint4*)&AsH[base];
                uint4 al = *(const uint4*)&AsL[base];
#pragma unroll
                for (int nt = 0; nt < 4; ++nt) {
                    mma_tf32(acc[mt][nt][0], acc[mt][nt][1], acc[mt][nt][2], acc[mt][nt][3],
                             al.x, al.y, al.z, al.w, bh[nt].x, bh[nt].y);
                    mma_tf32(acc[mt][nt][0], acc[mt][nt][1], acc[mt][nt][2], acc[mt][nt][3],
                             ah.x, ah.y, ah.z, ah.w, bl[nt].x, bl[nt].y);
                    mma_tf32(acc[mt][nt][0], acc[mt][nt][1], acc[mt][nt][2], acc[mt][nt][3],
                             ah.x, ah.y, ah.z, ah.w, bh[nt].x, bh[nt].y);
                }
            }
        }
        __syncthreads();
    }

#pragma unroll
    for (int mt = 0; mt < 2; ++mt) {
#pragma unroll
        for (int nt = 0; nt < 4; ++nt) {
            const int c = n0g + warpN*32 + nt*8 + (lane & 3) * 2;
#pragma unroll
            for (int half = 0; half < 2; ++half) {
                const int r  = m0 + warpM*32 + mt*16 + (lane >> 2) + half*8;
                const int bb = r >> 11, ss = r & (Ss - 1);
                float2 v;
                v.x = sigmoidf_fast(acc[mt][nt][half*2 + 0]);
                v.y = sigmoidf_fast(acc[mt][nt][half*2 + 1]);
                if (mode == 0) {
                    const int h = c >> 4, d = c & 15;
                    *(float2*)&g_pq[(((bb*Hh + h)*Ss) + ss)*QKBd + d] = v;
                } else if (mode == 1) {
                    const int kv = c >> 4, d = c & 15;
                    *(float2*)&g_pk[(((bb*KVh + kv)*Ss) + ss)*QKBd + d] = v;
                } else {
                    const int kv = c >> 5, d = c & 31;
                    *(float2*)&g_pv[(((bb*KVh + kv)*Ss) + ss)*VBd + d] = v;
                }
            }
        }
    }
}

// ---------------- Kernel 1b: split K/V into frag-layout hi/lo + sk ----------
// One thread per key (B*KV*S = 16384 threads).
__global__ __launch_bounds__(256) void split_kv()
{
    const int t = blockIdx.x * 256 + threadIdx.x;     // global key index
    const int bbkv = t >> 11;                         // / Ss
    const int tpos = t & (Ss - 1);
    const int kt   = tpos >> 6;
    const int tloc = tpos & 63;

    // ---- K: 16 bits -> frag layout + sk ----
    {
        const float4* kp = (const float4*)&g_pk[t * QKBd];
        float4 a = kp[0], b = kp[1], c = kp[2], d = kp[3];
        float kv[16] = {a.x,a.y,a.z,a.w, b.x,b.y,b.z,b.w,
                        c.x,c.y,c.z,c.w, d.x,d.y,d.z,d.w};
        float s = 0.f;
#pragma unroll
        for (int u = 0; u < 16; ++u) s += kv[u];
        g_sk[t] = s;

        const int base = (bbkv * NTILES + kt) * 1024;
        const int n8t = tloc >> 3, nc = tloc & 7;
#pragma unroll
        for (int u = 0; u < 16; ++u) {
            const int k8 = u >> 3, kr = u & 7;
            const int idx = base + ((n8t*2 + k8)*32 + ((nc << 2) | (kr & 3)))*2 + (kr >> 2);
            const unsigned hb = f2tf(kv[u]);
            g_kfh[idx] = hb;
            g_kfl[idx] = f2tf(kv[u] - __uint_as_float(hb));
        }
    }
    // ---- V: 32 dims -> frag layout ----
    {
        const float4* vp = (const float4*)&g_pv[t * VBd];
        float vv[32];
#pragma unroll
        for (int q = 0; q < 8; ++q) {
            float4 x = vp[q];
            vv[q*4+0] = x.x; vv[q*4+1] = x.y; vv[q*4+2] = x.z; vv[q*4+3] = x.w;
        }
        const int base = (bbkv * NTILES + kt) * 2048;
        const int k8 = tloc >> 3, kr = tloc & 7;
#pragma unroll
        for (int u = 0; u < 32; ++u) {
            const int n8 = u >> 3, nc = u & 7;
            const int idx = base + (n8*8 + k8)*64 + ((nc << 2) | (kr & 3))*2 + (kr >> 2);
            const unsigned hb = f2tf(vv[u]);
            g_vfh[idx] = hb;
            g_vfl[idx] = f2tf(vv[u] - __uint_as_float(hb));
        }
    }
}

// ---------------- Kernel 1c: bias = e0 @ Wo (partial sums + atomics) ---------
__global__ void zero_bias()
{
    g_bias[blockIdx.x * 256 + threadIdx.x] = 0.f;
}
__global__ void bias_part(const float* __restrict__ Wo, const float* __restrict__ e0)
{
    const int d  = blockIdx.x * 128 + threadIdx.x;
    const int j0 = blockIdx.y * 64;
    float s = 0.f;
#pragma unroll 8
    for (int jj = 0; jj < 64; ++jj)
        s = fmaf(e0[j0 + jj], Wo[(j0 + jj) * Dd + d], s);
    atomicAdd(&g_bias[d], s);
}

// ---------------- Kernel 2: causal flash attention (tf32, smem-free) ---------
// S = (2*Q)·K^T - sk ; P = exp(S) ; O = P·V / rowsum(P).
// K/V fragments (hi/lo) read directly from pre-split global arrays.
// Block = 128 threads (4 warps); warp owns 16 queries; no smem, no barriers.
#define ATTN_SLAB(DIAG)                                                         \
    do {                                                                        \
        uint2 kh0 = *(const uint2*)&kh[(nt*2+0)*64 + lane*2];                   \
        uint2 kl0 = *(const uint2*)&kl[(nt*2+0)*64 + lane*2];                   \
        uint2 kh1 = *(const uint2*)&kh[(nt*2+1)*64 + lane*2];                   \
        uint2 kl1 = *(const uint2*)&kl[(nt*2+1)*64 + lane*2];                   \
        float s0=0.f, s1=0.f, s2=0.f, s3=0.f;                                   \
        mma_tf32(s0,s1,s2,s3, aql[0][0],aql[0][1],aql[0][2],aql[0][3], kh0.x,kh0.y); \
        mma_tf32(s0,s1,s2,s3, aqh[0][0],aqh[0][1],aqh[0][2],aqh[0][3], kl0.x,kl0.y); \
        mma_tf32(s0,s1,s2,s3, aqh[0][0],aqh[0][1],aqh[0][2],aqh[0][3], kh0.x,kh0.y); \
        mma_tf32(s0,s1,s2,s3, aql[1][0],aql[1][1],aql[1][2],aql[1][3], kh1.x,kh1.y); \
        mma_tf32(s0,s1,s2,s3, aqh[1][0],aqh[1][1],aqh[1][2],aqh[1][3], kl1.x,kl1.y); \
        mma_tf32(s0,s1,s2,s3, aqh[1][0],aqh[1][1],aqh[1][2],aqh[1][3], kh1.x,kh1.y); \
        const float2 skp = *(const float2*)&skt[nt*8 + c4*2];                   \
        float e0 = __expf(s0 - skp.x);                                          \
        float e1 = __expf(s1 - skp.y);                                          \
        float e2 = __expf(s2 - skp.x);                                          \
        float e3 = __expf(s3 - skp.y);                                          \
        if (DIAG) {                                                             \
            const int keyb = nt*8 + c4*2;                                       \
            const int ql0  = w*16 + r;                                          \
            if (keyb     > ql0)     e0 = 0.f;                                   \
            if (keyb + 1 > ql0)     e1 = 0.f;                                   \
            if (keyb     > ql0 + 8) e2 = 0.f;                                   \
            if (keyb + 1 > ql0 + 8) e3 = 0.f;                                   \
        }                                                                       \
        lr  += e0 + e1;                                                         \
        lr8 += e2 + e3;                                                         \
        const int ls  = (lane & ~3) | (c4 >> 1);                                \
        const int ls2 = ls + 2;                                                 \
        const float t00 = __shfl_sync(0xffffffffu, e0, ls);                     \
        const float t01 = __shfl_sync(0xffffffffu, e1, ls);                     \
        const float t10 = __shfl_sync(0xffffffffu, e2, ls);                     \
        const float t11 = __shfl_sync(0xffffffffu, e3, ls);                     \
        const float u00 = __shfl_sync(0xffffffffu, e0, ls2);                    \
        const float u01 = __shfl_sync(0xffffffffu, e1, ls2);                    \
        const float u10 = __shfl_sync(0xffffffffu, e2, ls2);                    \
        const float u11 = __shfl_sync(0xffffffffu, e3, ls2);                    \
        const bool odd = (c4 & 1);                                              \
        const float pv0 = odd ? t01 : t00;                                      \
        const float pv1 = odd ? t11 : t10;                                      \
        const float pv2 = odd ? u01 : u00;                                      \
        const float pv3 = odd ? u11 : u10;                                      \
        unsigned ph[4], pl[4];                                                  \
        {                                                                       \
            const float pvv[4] = {pv0, pv1, pv2, pv3};                          \
            for (int j = 0; j < 4; ++j) {                                       \
                const unsigned hb = f2tf(pvv[j]);                               \
                ph[j] = hb;                                                     \
                pl[j] = f2tf(pvv[j] - __uint_as_float(hb));                     \
            }                                                                   \
        }                                                                       \
        for (int ntv = 0; ntv < 4; ++ntv) {                                     \
            uint2 bh = *(const uint2*)&vh[(ntv*8 + nt)*64 + lane*2];            \
            uint2 bl = *(const uint2*)&vl[(ntv*8 + nt)*64 + lane*2];            \
            mma_tf32(o[ntv][0],o[ntv][1],o[ntv][2],o[ntv][3],                   \
                     pl[0],pl[1],pl[2],pl[3], bh.x, bh.y);                      \
            mma_tf32(o[ntv][0],o[ntv][1],o[ntv][2],o[ntv][3],                   \
                     ph[0],ph[1],ph[2],ph[3], bl.x, bl.y);                      \
            mma_tf32(o[ntv][0],o[ntv][1],o[ntv][2],o[ntv][3],                   \
                     ph[0],ph[1],ph[2],ph[3], bh.x, bh.y);                      \
        }                                                                       \
    } while (0)

__global__ __launch_bounds__(128) void attn_mma()
{
    const int qt   = (NTILES - 1) - blockIdx.x;   // heavy tiles first
    const int h    = blockIdx.y;
    const int bb   = blockIdx.z;
    const int kvh  = h >> 2;
    const int tid  = threadIdx.x;
    const int lane = tid & 31;
    const int w    = tid >> 5;
    const int q0   = qt * 64;
    const int r    = lane >> 2;
    const int c4   = lane & 3;

    const float* __restrict__ pqb = &g_pq[((bb*Hh + h)*Ss) * QKBd];
    const int kvt = (bb*KVh + kvh) * NTILES;
    const unsigned* __restrict__ kfh = &g_kfh[kvt * 1024];
    const unsigned* __restrict__ kfl = &g_kfl[kvt * 1024];
    const unsigned* __restrict__ vfh = &g_vfh[kvt * 2048];
    const unsigned* __restrict__ vfl = &g_vfl[kvt * 2048];
    const float*    __restrict__ skb = &g_sk[(bb*KVh + kvh) * Ss];

    // ---- Q fragments (pre-scaled by 2, hi/lo split) ----
    unsigned aqh[2][4], aql[2][4];
    const int qrow0 = q0 + w*16 + r;
#pragma unroll
    for (int k8 = 0; k8 < 2; ++k8) {
#pragma unroll
        for (int j = 0; j < 4; ++j) {
            const int row = qrow0 + ((j & 1) ? 8 : 0);
            const int col = k8*8 + c4 + ((j & 2) ? 4 : 0);
            const float x = 2.f * pqb[row*QKBd + col];
            const unsigned hb = f2tf(x);
            aqh[k8][j] = hb;
            aql[k8][j] = f2tf(x - __uint_as_float(hb));
        }
    }

    float o[4][4];
#pragma unroll
    for (int ntv = 0; ntv < 4; ++ntv)
#pragma unroll
        for (int j = 0; j < 4; ++j) o[ntv][j] = 0.f;
    float lr = 0.f, lr8 = 0.f;

    // ---- full (non-diagonal) tiles ----
    for (int kt = 0; kt < qt; ++kt) {
        const unsigned* __restrict__ kh = kfh + kt*1024;
        const unsigned* __restrict__ kl = kfl + kt*1024;
        const unsigned* __restrict__ vh = vfh + kt*2048;
        const unsigned* __restrict__ vl = vfl + kt*2048;
        const float*    __restrict__ skt = skb + kt*64;
#pragma unroll
        for (int nt = 0; nt < 8; ++nt) {
            ATTN_SLAB(false);
        }
    }
    // ---- diagonal tile (causal; warps skip fully-masked slabs) ----
    {
        const unsigned* __restrict__ kh = kfh + qt*1024;
        const unsigned* __restrict__ kl = kfl + qt*1024;
        const unsigned* __restrict__ vh = vfh + qt*2048;
        const unsigned* __restrict__ vl = vfl + qt*2048;
        const float*    __restrict__ skt = skb + qt*64;
        const int ntmax = w*2 + 2;
        for (int nt = 0; nt < ntmax; ++nt) {
            ATTN_SLAB(true);
        }
    }

    // ---- normalize + write ----
    lr  += __shfl_xor_sync(0xffffffffu, lr, 1);
    lr  += __shfl_xor_sync(0xffffffffu, lr, 2);
    lr8 += __shfl_xor_sync(0xffffffffu, lr8, 1);
    lr8 += __shfl_xor_sync(0xffffffffu, lr8, 2);
    const float ir  = 1.f / lr;
    const float ir8 = 1.f / lr8;

    float* orow0 = &g_vh[(bb*Ss + qrow0) * HVB + h*VBd];
    float* orow8 = orow0 + 8 * HVB;
#pragma unroll
    for (int ntv = 0; ntv < 4; ++ntv) {
        const int d0 = ntv*8 + c4*2;
        float2 v0; v0.x = o[ntv][0] * ir;  v0.y = o[ntv][1] * ir;
        float2 v8; v8.x = o[ntv][2] * ir8; v8.y = o[ntv][3] * ir8;
        *(float2*)&orow0[d0] = v0;
        *(float2*)&orow8[d0] = v8;
    }
}

// ---------------- Kernel 3: out = ((e1-e0) o vh) @ Wo + bias (tf32 3-term) ---
__global__ __launch_bounds__(256) void out_tf32(
    const float* __restrict__ Wo, const float* __restrict__ e0,
    const float* __restrict__ e1, float* __restrict__ out)
{
    __shared__ unsigned AsH[4096];
    __shared__ unsigned AsL[4096];
    __shared__ unsigned BsH[2048];
    __shared__ unsigned BsL[2048];
    __shared__ float scs[HVB];

    const int tid  = threadIdx.x;
    const int lane = tid & 31;
    const int warp = tid >> 5;
    const int warpM = warp & 3;
    const int warpN = warp >> 2;
    const int m0  = blockIdx.x * 128;
    const int n0g = blockIdx.y * 64;

    scs[tid]       = e1[tid]       - e0[tid];
    scs[tid + 256] = e1[tid + 256] - e0[tid + 256];
    __syncthreads();

    float acc[2][4][4];
#pragma unroll
    for (int mt = 0; mt < 2; ++mt)
#pragma unroll
        for (int nt = 0; nt < 4; ++nt)
#pragma unroll
            for (int j = 0; j < 4; ++j) acc[mt][nt][j] = 0.f;

    const int ar  = tid >> 1;
    const int acb = (tid & 1) * 16;
    const int bkr = tid >> 3;
    const int bnb = (tid & 7) * 8;

    for (int k0 = 0; k0 < HVB; k0 += 32) {
        {
            const float* Ap = &g_vh[(m0 + ar) * HVB + k0 + acb];
            float4 q0 = *(const float4*)(Ap + 0);
            float4 q1 = *(const float4*)(Ap + 4);
            float4 q2 = *(const float4*)(Ap + 8);
            float4 q3 = *(const float4*)(Ap + 12);
            float av[16] = {q0.x,q0.y,q0.z,q0.w, q1.x,q1.y,q1.z,q1.w,
                            q2.x,q2.y,q2.z,q2.w, q3.x,q3.y,q3.z,q3.w};
            const int r16 = ar & 15, mt = ar >> 4;
#pragma unroll
            for (int u = 0; u < 16; ++u) {
                const int c  = acb + u;
                const int k8 = c >> 3, c8 = c & 7;
                const int l2 = ((r16 & 7) << 2) | (c8 & 3);
                const int j  = (r16 >> 3) | (((c8 >> 2) & 1) << 1);
                const int idx = ((mt * 4 + k8) * 32 + l2) * 4 + j;
                const float x = av[u] * scs[k0 + c];
                const unsigned hb = f2tf(x);
                AsH[idx] = hb;
                AsL[idx] = f2tf(x - __uint_as_float(hb));
            }
        }
        {
            const float* Wp = &Wo[(k0 + bkr) * Dd + n0g + bnb];
            float4 w0 = *(const float4*)(Wp + 0);
            float4 w1 = *(const float4*)(Wp + 4);
            float wv[8] = {w0.x,w0.y,w0.z,w0.w, w1.x,w1.y,w1.z,w1.w};
            const int k8 = bkr >> 3, krr = bkr & 7;
#pragma unroll
            for (int u = 0; u < 8; ++u) {
                const int nc = bnb + u;
                const int n8t = nc >> 3, ncc = nc & 7;
                const int idx = ((n8t * 4 + k8) * 32 + ((ncc << 2) | (krr & 3))) * 2 + (krr >> 2);
                const float x = wv[u];
                const unsigned hb = f2tf(x);
                BsH[idx] = hb;
                BsL[idx] = f2tf(x - __uint_as_float(hb));
            }
        }
        __syncthreads();

#pragma unroll
        for (int k8 = 0; k8 < 4; ++k8) {
            uint2 bh[4], bl[4];
#pragma unroll
            for (int nt = 0; nt < 4; ++nt) {
                const int bi = (((warpN*4 + nt) * 4 + k8) * 32 + lane) * 2;
                bh[nt] = *(const uint2*)&BsH[bi];
                bl[nt] = *(const uint2*)&BsL[bi];
            }
#pragma unroll
            for (int mt = 0; mt < 2; ++mt) {
                const int base = (((warpM*2 + mt) * 4 + k8) * 32 + lane) * 4;
                uint4 ah = *(const uint4*)&AsH[base];
                uint4 al = *(const uint4*)&AsL[base];
#pragma unroll
                for (int nt = 0; nt < 4; ++nt) {
                    mma_tf32(acc[mt][nt][0], acc[mt][nt][1], acc[mt][nt][2], acc[mt][nt][3],
                             al.x, al.y, al.z, al.w, bh[nt].x, bh[nt].y);
                    mma_tf32(acc[mt][nt][0], acc[mt][nt][1], acc[mt][nt][2], acc[mt][nt][3],
                             ah.x, ah.y, ah.z, ah.w, bl[nt].x, bl[nt].y);
                    mma_tf32(acc[mt][nt][0], acc[mt][nt][1], acc[mt][nt][2], acc[mt][nt][3],
                             ah.x, ah.y, ah.z, ah.w, bh[nt].x, bh[nt].y);
                }
            }
        }
        __syncthreads();
    }

#pragma unroll
    for (int mt = 0; mt < 2; ++mt) {
#pragma unroll
        for (int nt = 0; nt < 4; ++nt) {
            const int c = n0g + warpN*32 + nt*8 + (lane & 3) * 2;
            const float2 bv = *(const float2*)&g_bias[c];
#pragma unroll
            for (int half = 0; half < 2; ++half) {
                const int r = m0 + warpM*32 + mt*16 + (lane >> 2) + half*8;
                float2 v;
                v.x = acc[mt][nt][half*2 + 0] + bv.x;
                v.y = acc[mt][nt][half*2 + 1] + bv.y;
                *(float2*)&out[r*Dd + c] = v;
            }
        }
    }
}

// ---------------- launch -----------------------------------------------------
extern "C" void kernel_launch(void* const* d_in, const int* in_sizes, int n_in,
                              void* d_out, int out_size)
{
    const float* hs = (const float*)d_in[0];
    const float* Wq = (const float*)d_in[1];
    const float* Wk = (const float*)d_in[2];
    const float* Wv = (const float*)d_in[3];
    const float* Wo = (const float*)d_in[4];
    const float* e0 = (const float*)d_in[5];
    const float* e1 = (const float*)d_in[6];
    float* out = (float*)d_out;

    proj_tf32<<<dim3(MROWS/128, 7), 256>>>(hs, Wq, Wk, Wv);
    split_kv<<<(Bb*KVh*Ss)/256, 256>>>();
    zero_bias<<<Dd/256, 256>>>();
    bias_part<<<dim3(Dd/128, 8), 128>>>(Wo, e0);
    attn_mma<<<dim3(NTILES, Hh, Bb), 128>>>();
    out_tf32<<<dim3(MROWS/128, Dd/64), 256>>>(Wo, e0, e1, out);
}

// round 14
// speedup vs baseline: 1.2745x; 1.2745x over previous
#include <cuda_runtime.h>

// Problem dims (fixed)
#define Bb   2
#define Ss   2048
#define Dd   1024
#define Hh   16
#define KVh  4
#define QKBd 16
#define VBd  32
#define MROWS (Bb*Ss)          // 4096
#define HVB   (Hh*VBd)         // 512
#define NTILES (Ss/64)         // 32

// ---------------- scratch (static device arrays; no allocation) -------------
__device__ __align__(16) float g_pq[Bb*Hh*Ss*QKBd];    // [(b*H+h)*S+s][16]
__device__ __align__(16) float g_pk[Bb*KVh*Ss*QKBd];   // [(b*KV+kv)*S+t][16]
__device__ __align__(16) float g_sk[Bb*KVh*Ss];        // row sums of pk
__device__ __align__(16) float g_pv[Bb*KVh*Ss*VBd];    // [(b*KV+kv)*S+t][32]
__device__ __align__(16) float g_vh[Bb*Ss*HVB];        // [b*S+s][h*32+j]
__device__ __align__(16) float g_bias[Dd];             // e0 @ Wo

// Pre-split K/V in MMA B-fragment layout (hi/lo tf32), one tile = 64 keys.
// K tile: 8 n8 x 2 k8 x 32 lane x 2 j = 1024 u32.  V tile: 4 n8 x 8 k8 x 64 = 2048 u32.
__device__ __align__(16) unsigned g_kfh[Bb*KVh*NTILES*1024];
__device__ __align__(16) unsigned g_kfl[Bb*KVh*NTILES*1024];
__device__ __align__(16) unsigned g_vfh[Bb*KVh*NTILES*2048];
__device__ __align__(16) unsigned g_vfl[Bb*KVh*NTILES*2048];

__device__ __forceinline__ float sigmoidf_fast(float x) {
    return __fdividef(1.f, 1.f + __expf(-x));
}
__device__ __forceinline__ unsigned f2tf(float x) {
    unsigned u; asm("cvt.rna.tf32.f32 %0, %1;" : "=r"(u) : "f"(x)); return u;
}
__device__ __forceinline__ void mma_tf32(
    float& c0, float& c1, float& c2, float& c3,
    unsigned a0, unsigned a1, unsigned a2, unsigned a3,
    unsigned b0, unsigned b1)
{
    asm("mma.sync.aligned.m16n8k8.row.col.f32.tf32.tf32.f32 "
        "{%0,%1,%2,%3},{%4,%5,%6,%7},{%8,%9},{%0,%1,%2,%3};"
        : "+f"(c0), "+f"(c1), "+f"(c2), "+f"(c3)
        : "r"(a0), "r"(a1), "r"(a2), "r"(a3), "r"(b0), "r"(b1));
}
#define CP16(dstS, srcG) \
    asm volatile("cp.async.cg.shared.global [%0], [%1], 16;" :: "r"(dstS), "l"(srcG))

// Fragment-permuted smem layout (GEMMs):
// A tile: blocks of 128 u32; elem (r16,c8): lane=((r&7)<<2)|(c&3), j=(r>>3)|(((c>>2)&1)<<1)
// B tile: blocks of 64 u32;  elem (kr,nc):  lane=(nc<<2)|(kr&3), j=kr>>2

// ---------------- Kernel 1: fused QKV projection (tf32 3-term emulation) ----
__global__ __launch_bounds__(256) void proj_tf32(
    const float* __restrict__ A,
    const float* __restrict__ Wq, const float* __restrict__ Wk,
    const float* __restrict__ Wv)
{
    __shared__ unsigned AsH[4096];
    __shared__ unsigned AsL[4096];
    __shared__ unsigned BsH[2048];
    __shared__ unsigned BsL[2048];

    const int tid  = threadIdx.x;
    const int lane = tid & 31;
    const int warp = tid >> 5;
    const int warpM = warp & 3;
    const int warpN = warp >> 2;
    const int m0 = blockIdx.x * 128;

    const float* W; int N, n0g, mode;
    const int yb = blockIdx.y;
    if (yb < 4)       { W = Wq; N = 256; n0g = yb * 64;       mode = 0; }
    else if (yb == 4) { W = Wk; N = 64;  n0g = 0;             mode = 1; }
    else              { W = Wv; N = 128; n0g = (yb - 5) * 64; mode = 2; }

    float acc[2][4][4];
#pragma unroll
    for (int mt = 0; mt < 2; ++mt)
#pragma unroll
        for (int nt = 0; nt < 4; ++nt)
#pragma unroll
            for (int j = 0; j < 4; ++j) acc[mt][nt][j] = 0.f;

    const int ar  = tid >> 1;
    const int acb = (tid & 1) * 16;
    const int bkr = tid >> 3;
    const int bnb = (tid & 7) * 8;

    for (int k0 = 0; k0 < Dd; k0 += 32) {
        {
            const float* Ap = &A[(m0 + ar) * Dd + k0 + acb];
            float4 q0 = *(const float4*)(Ap + 0);
            float4 q1 = *(const float4*)(Ap + 4);
            float4 q2 = *(const float4*)(Ap + 8);
            float4 q3 = *(const float4*)(Ap + 12);
            float av[16] = {q0.x,q0.y,q0.z,q0.w, q1.x,q1.y,q1.z,q1.w,
                            q2.x,q2.y,q2.z,q2.w, q3.x,q3.y,q3.z,q3.w};
            const int r16 = ar & 15, mt = ar >> 4;
#pragma unroll
            for (int u = 0; u < 16; ++u) {
                const int c  = acb + u;
                const int k8 = c >> 3, c8 = c & 7;
                const int l2 = ((r16 & 7) << 2) | (c8 & 3);
                const int j  = (r16 >> 3) | (((c8 >> 2) & 1) << 1);
                const int idx = ((mt * 4 + k8) * 32 + l2) * 4 + j;
                const float x = av[u];
                const unsigned hb = f2tf(x);
                AsH[idx] = hb;
                AsL[idx] = f2tf(x - __uint_as_float(hb));
            }
        }
        {
            const float* Wp = &W[(k0 + bkr) * N + n0g + bnb];
            float4 w0 = *(const float4*)(Wp + 0);
            float4 w1 = *(const float4*)(Wp + 4);
            float wv[8] = {w0.x,w0.y,w0.z,w0.w, w1.x,w1.y,w1.z,w1.w};
            const int k8 = bkr >> 3, krr = bkr & 7;
#pragma unroll
            for (int u = 0; u < 8; ++u) {
                const int nc = bnb + u;
                const int n8t = nc >> 3, ncc = nc & 7;
                const int idx = ((n8t * 4 + k8) * 32 + ((ncc << 2) | (krr & 3))) * 2 + (krr >> 2);
                const float x = wv[u];
                const unsigned hb = f2tf(x);
                BsH[idx] = hb;
                BsL[idx] = f2tf(x - __uint_as_float(hb));
            }
        }
        __syncthreads();

#pragma unroll
        for (int k8 = 0; k8 < 4; ++k8) {
            uint2 bh[4], bl[4];
#pragma unroll
            for (int nt = 0; nt < 4; ++nt) {
                const int bi = (((warpN*4 + nt) * 4 + k8) * 32 + lane) * 2;
                bh[nt] = *(const uint2*)&BsH[bi];
                bl[nt] = *(const uint2*)&BsL[bi];
            }
#pragma unroll
            for (int mt = 0; mt < 2; ++mt) {
                const int base = (((warpM*2 + mt) * 4 + k8) * 32 + lane) * 4;
                uint4 ah = *(const uint4*)&AsH[base];
                uint4 al = *(const uint4*)&AsL[base];
#pragma unroll
                for (int nt = 0; nt < 4; ++nt) {
                    mma_tf32(acc[mt][nt][0], acc[mt][nt][1], acc[mt][nt][2], acc[mt][nt][3],
                             al.x, al.y, al.z, al.w, bh[nt].x, bh[nt].y);
                    mma_tf32(acc[mt][nt][0], acc[mt][nt][1], acc[mt][nt][2], acc[mt][nt][3],
                             ah.x, ah.y, ah.z, ah.w, bl[nt].x, bl[nt].y);
                    mma_tf32(acc[mt][nt][0], acc[mt][nt][1], acc[mt][nt][2], acc[mt][nt][3],
                             ah.x, ah.y, ah.z, ah.w, bh[nt].x, bh[nt].y);
                }
            }
        }
        __syncthreads();
    }

#pragma unroll
    for (int mt = 0; mt < 2; ++mt) {
#pragma unroll
        for (int nt = 0; nt < 4; ++nt) {
            const int c = n0g + warpN*32 + nt*8 + (lane & 3) * 2;
#pragma unroll
            for (int half = 0; half < 2; ++half) {
                const int r  = m0 + warpM*32 + mt*16 + (lane >> 2) + half*8;
                const int bb = r >> 11, ss = r & (Ss - 1);
                float2 v;
                v.x = sigmoidf_fast(acc[mt][nt][half*2 + 0]);
                v.y = sigmoidf_fast(acc[mt][nt][half*2 + 1]);
                if (mode == 0) {
                    const int h = c >> 4, d = c & 15;
                    *(float2*)&g_pq[(((bb*Hh + h)*Ss) + ss)*QKBd + d] = v;
                } else if (mode == 1) {
                    const int kv = c >> 4, d = c & 15;
                    *(float2*)&g_pk[(((bb*KVh + kv)*Ss) + ss)*QKBd + d] = v;
                } else {
                    const int kv = c >> 5, d = c & 31;
                    *(float2*)&g_pv[(((bb*KVh + kv)*Ss) + ss)*VBd + d] = v;
                }
            }
        }
    }
}

// ---------------- Kernel 1b: split K/V into frag-layout hi/lo + sk ----------
__global__ __launch_bounds__(256) void split_kv()
{
    const int t = blockIdx.x * 256 + threadIdx.x;     // global key index
    const int bbkv = t >> 11;
    const int tpos = t & (Ss - 1);
    const int kt   = tpos >> 6;
    const int tloc = tpos & 63;

    {
        const float4* kp = (const float4*)&g_pk[t * QKBd];
        float4 a = kp[0], b = kp[1], c = kp[2], d = kp[3];
        float kv[16] = {a.x,a.y,a.z,a.w, b.x,b.y,b.z,b.w,
                        c.x,c.y,c.z,c.w, d.x,d.y,d.z,d.w};
        float s = 0.f;
#pragma unroll
        for (int u = 0; u < 16; ++u) s += kv[u];
        g_sk[t] = s;

        const int base = (bbkv * NTILES + kt) * 1024;
        const int n8t = tloc >> 3, nc = tloc & 7;
#pragma unroll
        for (int u = 0; u < 16; ++u) {
            const int k8 = u >> 3, kr = u & 7;
            const int idx = base + ((n8t*2 + k8)*32 + ((nc << 2) | (kr & 3)))*2 + (kr >> 2);
            const unsigned hb = f2tf(kv[u]);
            g_kfh[idx] = hb;
            g_kfl[idx] = f2tf(kv[u] - __uint_as_float(hb));
        }
    }
    {
        const float4* vp = (const float4*)&g_pv[t * VBd];
        float vv[32];
#pragma unroll
        for (int q = 0; q < 8; ++q) {
            float4 x = vp[q];
            vv[q*4+0] = x.x; vv[q*4+1] = x.y; vv[q*4+2] = x.z; vv[q*4+3] = x.w;
        }
        const int base = (bbkv * NTILES + kt) * 2048;
        const int k8 = tloc >> 3, kr = tloc & 7;
#pragma unroll
        for (int u = 0; u < 32; ++u) {
            const int n8 = u >> 3, nc = u & 7;
            const int idx = base + (n8*8 + k8)*64 + ((nc << 2) | (kr & 3))*2 + (kr >> 2);
            const unsigned hb = f2tf(vv[u]);
            g_vfh[idx] = hb;
            g_vfl[idx] = f2tf(vv[u] - __uint_as_float(hb));
        }
    }
}

// ---------------- Kernel 1c: bias = e0 @ Wo (partial sums + atomics) ---------
__global__ void zero_bias()
{
    g_bias[blockIdx.x * 256 + threadIdx.x] = 0.f;
}
__global__ void bias_part(const float* __restrict__ Wo, const float* __restrict__ e0)
{
    const int d  = blockIdx.x * 128 + threadIdx.x;
    const int j0 = blockIdx.y * 64;
    float s = 0.f;
#pragma unroll 8
    for (int jj = 0; jj < 64; ++jj)
        s = fmaf(e0[j0 + jj], Wo[(j0 + jj) * Dd + d], s);
    atomicAdd(&g_bias[d], s);
}

// ---------------- Kernel 2: causal flash attention -------------------------
// cp.async double-buffered smem staging of pre-split K/V fragments.
// S = (2*Q)·K^T - sk ; P = exp(S) ; O = P·V / rowsum(P).
#define ATTN_SLAB(DIAG)                                                         \
    do {                                                                        \
        uint2 kh0 = *(const uint2*)&kh[(nt*2+0)*64 + lane*2];                   \
        uint2 kl0 = *(const uint2*)&kl[(nt*2+0)*64 + lane*2];                   \
        uint2 kh1 = *(const uint2*)&kh[(nt*2+1)*64 + lane*2];                   \
        uint2 kl1 = *(const uint2*)&kl[(nt*2+1)*64 + lane*2];                   \
        float s0=0.f, s1=0.f, s2=0.f, s3=0.f;                                   \
        mma_tf32(s0,s1,s2,s3, aql[0][0],aql[0][1],aql[0][2],aql[0][3], kh0.x,kh0.y); \
        mma_tf32(s0,s1,s2,s3, aqh[0][0],aqh[0][1],aqh[0][2],aqh[0][3], kl0.x,kl0.y); \
        mma_tf32(s0,s1,s2,s3, aqh[0][0],aqh[0][1],aqh[0][2],aqh[0][3], kh0.x,kh0.y); \
        mma_tf32(s0,s1,s2,s3, aql[1][0],aql[1][1],aql[1][2],aql[1][3], kh1.x,kh1.y); \
        mma_tf32(s0,s1,s2,s3, aqh[1][0],aqh[1][1],aqh[1][2],aqh[1][3], kl1.x,kl1.y); \
        mma_tf32(s0,s1,s2,s3, aqh[1][0],aqh[1][1],aqh[1][2],aqh[1][3], kh1.x,kh1.y); \
        const float2 skp = *(const float2*)&skt[nt*8 + c4*2];                   \
        float e0 = __expf(s0 - skp.x);                                          \
        float e1 = __expf(s1 - skp.y);                                          \
        float e2 = __expf(s2 - skp.x);                                          \
        float e3 = __expf(s3 - skp.y);                                          \
        if (DIAG) {                                                             \
            const int keyb = nt*8 + c4*2;                                       \
            const int ql0  = w*16 + r;                                          \
            if (keyb     > ql0)     e0 = 0.f;                                   \
            if (keyb + 1 > ql0)     e1 = 0.f;                                   \
            if (keyb     > ql0 + 8) e2 = 0.f;                                   \
            if (keyb + 1 > ql0 + 8) e3 = 0.f;                                   \
        }                                                                       \
        lr  += e0 + e1;                                                         \
        lr8 += e2 + e3;                                                         \
        const int ls  = (lane & ~3) | (c4 >> 1);                                \
        const int ls2 = ls + 2;                                                 \
        const float t00 = __shfl_sync(0xffffffffu, e0, ls);                     \
        const float t01 = __shfl_sync(0xffffffffu, e1, ls);                     \
        const float t10 = __shfl_sync(0xffffffffu, e2, ls);                     \
        const float t11 = __shfl_sync(0xffffffffu, e3, ls);                     \
        const float u00 = __shfl_sync(0xffffffffu, e0, ls2);                    \
        const float u01 = __shfl_sync(0xffffffffu, e1, ls2);                    \
        const float u10 = __shfl_sync(0xffffffffu, e2, ls2);                    \
        const float u11 = __shfl_sync(0xffffffffu, e3, ls2);                    \
        const bool odd = (c4 & 1);                                              \
        const float pv0 = odd ? t01 : t00;                                      \
        const float pv1 = odd ? t11 : t10;                                      \
        const float pv2 = odd ? u01 : u00;                                      \
        const float pv3 = odd ? u11 : u10;                                      \
        unsigned ph[4], pl[4];                                                  \
        {                                                                       \
            const float pvv[4] = {pv0, pv1, pv2, pv3};                          \
            for (int j = 0; j < 4; ++j) {                                       \
                const unsigned hb = f2tf(pvv[j]);                               \
                ph[j] = hb;                                                     \
                pl[j] = f2tf(pvv[j] - __uint_as_float(hb));                     \
            }                                                                   \
        }                                                                       \
        for (int ntv = 0; ntv < 4; ++ntv) {                                     \
            uint2 bh = *(const uint2*)&vs_h[(ntv*8 + nt)*64 + lane*2];          \
            uint2 bl = *(const uint2*)&vs_l[(ntv*8 + nt)*64 + lane*2];          \
            mma_tf32(o[ntv][0],o[ntv][1],o[ntv][2],o[ntv][3],                   \
                     pl[0],pl[1],pl[2],pl[3], bh.x, bh.y);                      \
            mma_tf32(o[ntv][0],o[ntv][1],o[ntv][2],o[ntv][3],                   \
                     ph[0],ph[1],ph[2],ph[3], bl.x, bl.y);                      \
            mma_tf32(o[ntv][0],o[ntv][1],o[ntv][2],o[ntv][3],                   \
                     ph[0],ph[1],ph[2],ph[3], bh.x, bh.y);                      \
        }                                                                       \
    } while (0)

// Prefetch tile kt into buffer b (12 x 16B cp.async per thread + sk).
#define PREFETCH(b, kt)                                                         \
    do {                                                                        \
        const unsigned* gkh = kfh + (kt)*1024;                                  \
        const unsigned* gkl = kfl + (kt)*1024;                                  \
        const unsigned* gvh = vfh + (kt)*2048;                                  \
        const unsigned* gvl = vfl + (kt)*2048;                                  \
        const int o4 = tid * 4;                                                 \
        CP16((unsigned)__cvta_generic_to_shared(&Ksh[b][o4]),        gkh + o4); \
        CP16((unsigned)__cvta_generic_to_shared(&Ksh[b][512 + o4]),  gkh + 512 + o4); \
        CP16((unsigned)__cvta_generic_to_shared(&Ksl[b][o4]),        gkl + o4); \
        CP16((unsigned)__cvta_generic_to_shared(&Ksl[b][512 + o4]),  gkl + 512 + o4); \
        CP16((unsigned)__cvta_generic_to_shared(&Vsh[b][o4]),        gvh + o4); \
        CP16((unsigned)__cvta_generic_to_shared(&Vsh[b][512 + o4]),  gvh + 512 + o4); \
        CP16((unsigned)__cvta_generic_to_shared(&Vsh[b][1024 + o4]), gvh + 1024 + o4); \
        CP16((unsigned)__cvta_generic_to_shared(&Vsh[b][1536 + o4]), gvh + 1536 + o4); \
        CP16((unsigned)__cvta_generic_to_shared(&Vsl[b][o4]),        gvl + o4); \
        CP16((unsigned)__cvta_generic_to_shared(&Vsl[b][512 + o4]),  gvl + 512 + o4); \
        CP16((unsigned)__cvta_generic_to_shared(&Vsl[b][1024 + o4]), gvl + 1024 + o4); \
        CP16((unsigned)__cvta_generic_to_shared(&Vsl[b][1536 + o4]), gvl + 1536 + o4); \
        if (tid < 16)                                                           \
            CP16((unsigned)__cvta_generic_to_shared(&sksm[b][tid*4]),           \
                 skb + (kt)*64 + tid*4);                                        \
    } while (0)

__global__ __launch_bounds__(128) void attn_mma()
{
    __shared__ __align__(16) unsigned Ksh[2][1024], Ksl[2][1024];
    __shared__ __align__(16) unsigned Vsh[2][2048], Vsl[2][2048];
    __shared__ __align__(16) float    sksm[2][64];

    const int qt   = (NTILES - 1) - blockIdx.x;   // heavy tiles first
    const int h    = blockIdx.y;
    const int bb   = blockIdx.z;
    const int kvh  = h >> 2;
    const int tid  = threadIdx.x;
    const int lane = tid & 31;
    const int w    = tid >> 5;
    const int q0   = qt * 64;
    const int r    = lane >> 2;
    const int c4   = lane & 3;

    const float* __restrict__ pqb = &g_pq[((bb*Hh + h)*Ss) * QKBd];
    const int kvt = (bb*KVh + kvh) * NTILES;
    const unsigned* __restrict__ kfh = &g_kfh[kvt * 1024];
    const unsigned* __restrict__ kfl = &g_kfl[kvt * 1024];
    const unsigned* __restrict__ vfh = &g_vfh[kvt * 2048];
    const unsigned* __restrict__ vfl = &g_vfl[kvt * 2048];
    const float*    __restrict__ skb = &g_sk[(bb*KVh + kvh) * Ss];

    // kick off first tile's prefetch before doing Q work
    PREFETCH(0, 0);
    asm volatile("cp.async.commit_group;");

    // ---- Q fragments (pre-scaled by 2, hi/lo split) ----
    unsigned aqh[2][4], aql[2][4];
    const int qrow0 = q0 + w*16 + r;
#pragma unroll
    for (int k8 = 0; k8 < 2; ++k8) {
#pragma unroll
        for (int j = 0; j < 4; ++j) {
            const int row = qrow0 + ((j & 1) ? 8 : 0);
            const int col = k8*8 + c4 + ((j & 2) ? 4 : 0);
            const float x = 2.f * pqb[row*QKBd + col];
            const unsigned hb = f2tf(x);
            aqh[k8][j] = hb;
            aql[k8][j] = f2tf(x - __uint_as_float(hb));
        }
    }

    float o[4][4];
#pragma unroll
    for (int ntv = 0; ntv < 4; ++ntv)
#pragma unroll
        for (int j = 0; j < 4; ++j) o[ntv][j] = 0.f;
    float lr = 0.f, lr8 = 0.f;

    for (int kt = 0; kt <= qt; ++kt) {
        const int b = kt & 1;
        if (kt < qt) {
            PREFETCH(b ^ 1, kt + 1);
            asm volatile("cp.async.commit_group;");
            asm volatile("cp.async.wait_group 1;");
        } else {
            asm volatile("cp.async.wait_group 0;");
        }
        __syncthreads();

        const unsigned* kh   = Ksh[b];
        const unsigned* kl   = Ksl[b];
        const unsigned* vs_h = Vsh[b];
        const unsigned* vs_l = Vsl[b];
        const float*    skt  = sksm[b];

        if (kt < qt) {
#pragma unroll
            for (int nt = 0; nt < 8; ++nt) {
                ATTN_SLAB(false);
            }
        } else {
            const int ntmax = w*2 + 2;
            for (int nt = 0; nt < ntmax; ++nt) {
                ATTN_SLAB(true);
            }
        }
        __syncthreads();   // compute done before buffer b is refilled
    }

    // ---- normalize + write ----
    lr  += __shfl_xor_sync(0xffffffffu, lr, 1);
    lr  += __shfl_xor_sync(0xffffffffu, lr, 2);
    lr8 += __shfl_xor_sync(0xffffffffu, lr8, 1);
    lr8 += __shfl_xor_sync(0xffffffffu, lr8, 2);
    const float ir  = 1.f / lr;
    const float ir8 = 1.f / lr8;

    float* orow0 = &g_vh[(bb*Ss + qrow0) * HVB + h*VBd];
    float* orow8 = orow0 + 8 * HVB;
#pragma unroll
    for (int ntv = 0; ntv < 4; ++ntv) {
        const int d0 = ntv*8 + c4*2;
        float2 v0; v0.x = o[ntv][0] * ir;  v0.y = o[ntv][1] * ir;
        float2 v8; v8.x = o[ntv][2] * ir8; v8.y = o[ntv][3] * ir8;
        *(float2*)&orow0[d0] = v0;
        *(float2*)&orow8[d0] = v8;
    }
}

// ---------------- Kernel 3: out = ((e1-e0) o vh) @ Wo + bias (tf32 3-term) ---
__global__ __launch_bounds__(256) void out_tf32(
    const float* __restrict__ Wo, const float* __restrict__ e0,
    const float* __restrict__ e1, float* __restrict__ out)
{
    __shared__ unsigned AsH[4096];
    __shared__ unsigned AsL[4096];
    __shared__ unsigned BsH[2048];
    __shared__ unsigned BsL[2048];
    __shared__ float scs[HVB];

    const int tid  = threadIdx.x;
    const int lane = tid & 31;
    const int warp = tid >> 5;
    const int warpM = warp & 3;
    const int warpN = warp >> 2;
    const int m0  = blockIdx.x * 128;
    const int n0g = blockIdx.y * 64;

    scs[tid]       = e1[tid]       - e0[tid];
    scs[tid + 256] = e1[tid + 256] - e0[tid + 256];
    __syncthreads();

    float acc[2][4][4];
#pragma unroll
    for (int mt = 0; mt < 2; ++mt)
#pragma unroll
        for (int nt = 0; nt < 4; ++nt)
#pragma unroll
            for (int j = 0; j < 4; ++j) acc[mt][nt][j] = 0.f;

    const int ar  = tid >> 1;
    const int acb = (tid & 1) * 16;
    const int bkr = tid >> 3;
    const int bnb = (tid & 7) * 8;

    for (int k0 = 0; k0 < HVB; k0 += 32) {
        {
            const float* Ap = &g_vh[(m0 + ar) * HVB + k0 + acb];
            float4 q0 = *(const float4*)(Ap + 0);
            float4 q1 = *(const float4*)(Ap + 4);
            float4 q2 = *(const float4*)(Ap + 8);
            float4 q3 = *(const float4*)(Ap + 12);
            float av[16] = {q0.x,q0.y,q0.z,q0.w, q1.x,q1.y,q1.z,q1.w,
                            q2.x,q2.y,q2.z,q2.w, q3.x,q3.y,q3.z,q3.w};
            const int r16 = ar & 15, mt = ar >> 4;
#pragma unroll
            for (int u = 0; u < 16; ++u) {
                const int c  = acb + u;
                const int k8 = c >> 3, c8 = c & 7;
                const int l2 = ((r16 & 7) << 2) | (c8 & 3);
                const int j  = (r16 >> 3) | (((c8 >> 2) & 1) << 1);
                const int idx = ((mt * 4 + k8) * 32 + l2) * 4 + j;
                const float x = av[u] * scs[k0 + c];
                const unsigned hb = f2tf(x);
                AsH[idx] = hb;
                AsL[idx] = f2tf(x - __uint_as_float(hb));
            }
        }
        {
            const float* Wp = &Wo[(k0 + bkr) * Dd + n0g + bnb];
            float4 w0 = *(const float4*)(Wp + 0);
            float4 w1 = *(const float4*)(Wp + 4);
            float wv[8] = {w0.x,w0.y,w0.z,w0.w, w1.x,w1.y,w1.z,w1.w};
            const int k8 = bkr >> 3, krr = bkr & 7;
#pragma unroll
            for (int u = 0; u < 8; ++u) {
                const int nc = bnb + u;
                const int n8t = nc >> 3, ncc = nc & 7;
                const int idx = ((n8t * 4 + k8) * 32 + ((ncc << 2) | (krr & 3))) * 2 + (krr >> 2);
                const float x = wv[u];
                const unsigned hb = f2tf(x);
                BsH[idx] = hb;
                BsL[idx] = f2tf(x - __uint_as_float(hb));
            }
        }
        __syncthreads();

#pragma unroll
        for (int k8 = 0; k8 < 4; ++k8) {
            uint2 bh[4], bl[4];
#pragma unroll
            for (int nt = 0; nt < 4; ++nt) {
                const int bi = (((warpN*4 + nt) * 4 + k8) * 32 + lane) * 2;
                bh[nt] = *(const uint2*)&BsH[bi];
                bl[nt] = *(const uint2*)&BsL[bi];
            }
#pragma unroll
            for (int mt = 0; mt < 2; ++mt) {
                const int base = (((warpM*2 + mt) * 4 + k8) * 32 + lane) * 4;
                uint4 ah = *(const uint4*)&AsH[base];
                uint4 al = *(const uint4*)&AsL[base];
#pragma unroll
                for (int nt = 0; nt < 4; ++nt) {
                    mma_tf32(acc[mt][nt][0], acc[mt][nt][1], acc[mt][nt][2], acc[mt][nt][3],
                             al.x, al.y, al.z, al.w, bh[nt].x, bh[nt].y);
                    mma_tf32(acc[mt][nt][0], acc[mt][nt][1], acc[mt][nt][2], acc[mt][nt][3],
                             ah.x, ah.y, ah.z, ah.w, bl[nt].x, bl[nt].y);
                    mma_tf32(acc[mt][nt][0], acc[mt][nt][1], acc[mt][nt][2], acc[mt][nt][3],
                             ah.x, ah.y, ah.z, ah.w, bh[nt].x, bh[nt].y);
                }
            }
        }
        __syncthreads();
    }

#pragma unroll
    for (int mt = 0; mt < 2; ++mt) {
#pragma unroll
        for (int nt = 0; nt < 4; ++nt) {
            const int c = n0g + warpN*32 + nt*8 + (lane & 3) * 2;
            const float2 bv = *(const float2*)&g_bias[c];
#pragma unroll
            for (int half = 0; half < 2; ++half) {
                const int r = m0 + warpM*32 + mt*16 + (lane >> 2) + half*8;
                float2 v;
                v.x = acc[mt][nt][half*2 + 0] + bv.x;
                v.y = acc[mt][nt][half*2 + 1] + bv.y;
                *(float2*)&out[r*Dd + c] = v;
            }
        }
    }
}

// ---------------- launch -----------------------------------------------------
extern "C" void kernel_launch(void* const* d_in, const int* in_sizes, int n_in,
                              void* d_out, int out_size)
{
    const float* hs = (const float*)d_in[0];
    const float* Wq = (const float*)d_in[1];
    const float* Wk = (const float*)d_in[2];
    const float* Wv = (const float*)d_in[3];
    const float* Wo = (const float*)d_in[4];
    const float* e0 = (const float*)d_in[5];
    const float* e1 = (const float*)d_in[6];
    float* out = (float*)d_out;

    proj_tf32<<<dim3(MROWS/128, 7), 256>>>(hs, Wq, Wk, Wv);
    split_kv<<<(Bb*KVh*Ss)/256, 256>>>();
    zero_bias<<<Dd/256, 256>>>();
    bias_part<<<dim3(Dd/128, 8), 128>>>(Wo, e0);
    attn_mma<<<dim3(NTILES, Hh, Bb), 128>>>();
    out_tf32<<<dim3(MROWS/128, Dd/64), 256>>>(Wo, e0, e1, out);
}